// round 13
// baseline (speedup 1.0000x reference)
#include <cuda_runtime.h>
#include <cuda_bf16.h>
#include <math.h>
#include <stdint.h>

#define D       512
#define KALL    11
#define KTOP    4
#define DOM     10
#define BP      128
#define LPROBE  256
#define BG      64
#define LGAL    512
#define NSET    192
#define NPAIR   768
#define NCH     8

#define OFF_FP  0
#define OFF_TP  262144
#define OFF_FG  262254
#define OFF_TG  393326

// ------------------ scratch ------------------
__device__ float g_tp[2 * KALL * DOM];
__device__ float g_ps[NSET * NCH * D];
__device__ float g_pq[NSET * NCH * D];
__device__ float g_tpart[NSET * NCH * DOM];
__device__ int   g_cnt[KALL];
__device__ int   g_list[KALL * NPAIR];
__device__ float g_sum[NSET * 1024];
__device__ float g_pbP[KALL * 1024];
__device__ float g_pbG[KALL * 1024];
__device__ float g_h1[NPAIR * 1024];
__device__ float g_h2[NPAIR * 1024];
__device__ float g_ctxv[NPAIR * 512];
__device__ float g_ctx2[NPAIR * 512];
__device__ float g_sc[NSET * LGAL * KTOP];
__device__ float g_rn[NSET * LGAL];
__device__ float g_pp[NSET * NCH * 2 * KTOP * D];

__device__ __forceinline__ float wredsum(float v) {
    #pragma unroll
    for (int o = 16; o; o >>= 1) v += __shfl_xor_sync(0xffffffffu, v, o);
    return v;
}
__device__ __forceinline__ float wredmax(float v) {
    #pragma unroll
    for (int o = 16; o; o >>= 1) v = fmaxf(v, __shfl_xor_sync(0xffffffffu, v, o));
    return v;
}
__device__ __forceinline__ uint32_t smem_u32(const void* p) {
    uint32_t a;
    asm("{ .reg .u64 t; cvta.to.shared.u64 t, %1; cvt.u32.u64 %0, t; }" : "=r"(a) : "l"(p));
    return a;
}
__device__ __forceinline__ void ldsm4(uint32_t* r, uint32_t addr) {
    asm volatile("ldmatrix.sync.aligned.m8n8.x4.shared.b16 {%0,%1,%2,%3}, [%4];"
        : "=r"(r[0]), "=r"(r[1]), "=r"(r[2]), "=r"(r[3]) : "r"(addr));
}
__device__ __forceinline__ void mma16816(float* d, const uint32_t* a, uint32_t b0, uint32_t b1) {
    asm volatile("mma.sync.aligned.m16n8k16.row.col.f32.bf16.bf16.f32 "
        "{%0,%1,%2,%3}, {%4,%5,%6,%7}, {%8,%9}, {%0,%1,%2,%3};"
        : "+f"(d[0]), "+f"(d[1]), "+f"(d[2]), "+f"(d[3])
        : "r"(a[0]), "r"(a[1]), "r"(a[2]), "r"(a[3]), "r"(b0), "r"(b1));
}

// ------------------ init ------------------
__global__ void k_init(const float* __restrict__ proxP, const float* __restrict__ proxG,
                       const float* __restrict__ tW, const float* __restrict__ tb,
                       float* __restrict__ out) {
    __shared__ float tv[220];
    int tid = threadIdx.x;
    if (tid < KALL) g_cnt[tid] = 0;
    if (tid < 220) {
        int which = tid / 110;
        int rem = tid - which * 110;
        int k = rem / DOM, j = rem - k * DOM;
        const float* prox = which ? proxG : proxP;
        float acc = tb[j];
        for (int d = 0; d < D; d++) acc += prox[k * D + d] * tW[j * D + d];
        out[(which ? OFF_TG : OFF_TP) + k * DOM + j] = acc;
        tv[tid] = acc;
    }
    __syncthreads();
    if (tid < 220) {
        int base = (tid / DOM) * DOM;
        float nn = 0.f;
        #pragma unroll
        for (int j = 0; j < DOM; j++) nn += tv[base + j] * tv[base + j];
        float inv = 1.f / fmaxf(sqrtf(nn), 1e-12f);
        g_tp[tid] = tv[tid] * inv;
    }
}

// ------------------ proxy-part of layer1 folded into bias (per expert, per side) ------------------
// g_pbP[e, o] = b1[e, o] + sum_d W1[e, o, 1024 + d] * proxP[e, d]   (g_pbG likewise)
__global__ void __launch_bounds__(256) k_pbias(const float* __restrict__ W1, const float* __restrict__ b1,
                                               const float* __restrict__ proxP, const float* __restrict__ proxG) {
    __shared__ float sp[D], sg[D];
    int e = blockIdx.x;
    int tid = threadIdx.x, w = tid >> 5, lane = tid & 31;
    for (int i = tid; i < D; i += 256) {
        sp[i] = proxP[e * D + i];
        sg[i] = proxG[e * D + i];
    }
    __syncthreads();
    for (int o = w; o < 1024; o += 8) {
        const float* wr = W1 + ((size_t)e * 1024 + o) * 1536 + 1024;
        float ap = 0.f, ag = 0.f;
        #pragma unroll
        for (int i = 0; i < 16; i++) {
            int d = lane + i * 32;
            float wv = wr[d];
            ap += wv * sp[d];
            ag += wv * sg[d];
        }
        ap = wredsum(ap); ag = wredsum(ag);
        if (lane == 0) {
            float bb = b1[e * 1024 + o];
            g_pbP[e * 1024 + o] = bb + ap;
            g_pbG[e * 1024 + o] = bb + ag;
        }
    }
}

// ------------------ fused colstats + transform ------------------
__global__ void __launch_bounds__(256) k_fuse1(
        const float* __restrict__ probes, const float* __restrict__ gallery,
        const int* __restrict__ plen, const int* __restrict__ glen,
        const float* __restrict__ tW) {
    __shared__ float sWt[DOM * D];
    __shared__ float wsum[8][DOM];
    int s = blockIdx.x, ch = blockIdx.y, tid = threadIdx.x;
    bool isP = s < BP;
    int L = isP ? LPROBE : LGAL;
    const float* feat = isP ? probes + (size_t)s * LPROBE * D
                            : gallery + (size_t)(s - BP) * LGAL * D;
    int len = isP ? plen[s] : glen[s - BP];
    len = max(1, min(len, L));
    int cl = L >> 3;
    int r0 = ch * cl, r1 = min(len, r0 + cl);

    for (int i = tid; i < DOM * D; i += 256) sWt[i] = tW[i];

    {
        int d0 = tid, d1 = tid + 256;
        float s0 = 0.f, q0 = 0.f, s1 = 0.f, q1 = 0.f;
        for (int l = r0; l < r1; l++) {
            float x0 = feat[(size_t)l * D + d0];
            float x1 = feat[(size_t)l * D + d1];
            s0 += x0; q0 += x0 * x0;
            s1 += x1; q1 += x1 * x1;
        }
        size_t b = (size_t)(s * NCH + ch) * D;
        g_ps[b + d0] = s0; g_ps[b + d1] = s1;
        g_pq[b + d0] = q0; g_pq[b + d1] = q1;
    }
    __syncthreads();

    int w = tid >> 5, lane = tid & 31;
    float wacc[DOM];
    #pragma unroll
    for (int j = 0; j < DOM; j++) wacc[j] = 0.f;
    for (int base = r0 + w * 4; base < r1; base += 32) {
        float p[4][DOM];
        #pragma unroll
        for (int q = 0; q < 4; q++)
            #pragma unroll
            for (int j = 0; j < DOM; j++) p[q][j] = 0.f;
        const float* row0 = feat + (size_t)base * D;
        bool v1 = base + 1 < r1, v2 = base + 2 < r1, v3 = base + 3 < r1;
        #pragma unroll 4
        for (int ci = 0; ci < 16; ci++) {
            int col = lane + ci * 32;
            float x0 = row0[col];
            float x1 = v1 ? row0[D + col] : 0.f;
            float x2 = v2 ? row0[2 * D + col] : 0.f;
            float x3 = v3 ? row0[3 * D + col] : 0.f;
            #pragma unroll
            for (int j = 0; j < DOM; j++) {
                float wv = sWt[j * D + col];
                p[0][j] += x0 * wv;
                p[1][j] += x1 * wv;
                p[2][j] += x2 * wv;
                p[3][j] += x3 * wv;
            }
        }
        #pragma unroll
        for (int q = 0; q < 4; q++) {
            if (base + q < r1) {
                float nn = 0.f;
                #pragma unroll
                for (int j = 0; j < DOM; j++) { p[q][j] = wredsum(p[q][j]); nn += p[q][j] * p[q][j]; }
                float inv = 1.f / fmaxf(sqrtf(nn), 1e-12f);
                #pragma unroll
                for (int j = 0; j < DOM; j++) wacc[j] += p[q][j] * inv;
            }
        }
    }
    if (lane == 0) {
        #pragma unroll
        for (int j = 0; j < DOM; j++) wsum[w][j] = wacc[j];
    }
    __syncthreads();
    if (tid < DOM) {
        float a = 0.f;
        #pragma unroll
        for (int ww = 0; ww < 8; ww++) a += wsum[ww][tid];
        g_tpart[(s * NCH + ch) * DOM + tid] = a;
    }
}

// ------------------ prep: stats reduce + routing + set summaries ------------------
__global__ void __launch_bounds__(256) k_prep(
        const int* __restrict__ plen, const int* __restrict__ glen) {
    __shared__ float sMean[D], sVar[D];
    int s = blockIdx.x, tid = threadIdx.x;
    bool isP = s < BP;
    int L = isP ? LPROBE : LGAL;
    int len = isP ? plen[s] : glen[s - BP];
    len = max(1, min(len, L));
    float rl = 1.f / (float)len;
    #pragma unroll
    for (int h = 0; h < 2; h++) {
        int d = tid + h * 256;
        float sm = 0.f, sq = 0.f;
        #pragma unroll
        for (int ch = 0; ch < NCH; ch++) {
            size_t b = (size_t)(s * NCH + ch) * D + d;
            sm += g_ps[b]; sq += g_pq[b];
        }
        float m = sm * rl;
        sMean[d] = m;
        sVar[d] = sq * rl - m * m;
    }
    if (tid == 0) {
        float tv[DOM];
        #pragma unroll
        for (int j = 0; j < DOM; j++) {
            float a = 0.f;
            #pragma unroll
            for (int c = 0; c < NCH; c++) a += g_tpart[(s * NCH + c) * DOM + j];
            tv[j] = a;
        }
        const float* tp = g_tp + (isP ? 0 : KALL * DOM);
        float gs[KALL];
        for (int k = 0; k < KALL; k++) {
            float a = 0.f;
            #pragma unroll
            for (int j = 0; j < DOM; j++) a += tv[j] * tp[k * DOM + j];
            gs[k] = a;
        }
        bool used[KALL];
        for (int k = 0; k < KALL; k++) used[k] = false;
        for (int t = 0; t < KTOP; t++) {
            int best = -1; float bv = -3.4e38f;
            for (int k = 0; k < KALL; k++)
                if (!used[k] && gs[k] > bv) { bv = gs[k]; best = k; }
            used[best] = true;
            int pos = atomicAdd(&g_cnt[best], 1);
            g_list[best * NPAIR + pos] = s * KTOP + t;
        }
    }
    __syncthreads();
    for (int i = tid; i < D; i += 256) {
        g_sum[(size_t)s * 1024 + i]     = sMean[i];
        g_sum[(size_t)s * 1024 + D + i] = sVar[i];
    }
}

// ------------------ pipelined mma.sync bf16 expert-batched MLP layer ------------------
// SETX: X indexed by set (pid>>2), bias chosen per side (probe pid<512 vs gallery).
#define AST 72
template <int I, int O, int LD, bool SETX>
__global__ void __launch_bounds__(256) k_mlp_t(const float* __restrict__ W,
                                               const float* __restrict__ bP, const float* __restrict__ bG,
                                               const float* __restrict__ X, float* __restrict__ Y) {
    extern __shared__ __align__(16) __nv_bfloat16 sm[];
    __shared__ int pids[64];
    int e = blockIdx.x, o0 = blockIdx.y * 128, p0 = blockIdx.z * 64;
    int n = g_cnt[e];
    if (p0 >= n) return;
    int tid = threadIdx.x, wid = tid >> 5, lane = tid & 31;
    if (tid < 64) pids[tid] = (p0 + tid < n) ? g_list[e * NPAIR + p0 + tid] : -1;
    __syncthreads();

    __nv_bfloat16* As = sm;
    __nv_bfloat16* Bs = sm + 2 * 128 * AST;

    int wo = (wid >> 1) * 32;
    int wp = (wid & 1) * 32;
    float acc[2][4][4];
    #pragma unroll
    for (int mi = 0; mi < 2; mi++)
        #pragma unroll
        for (int ni = 0; ni < 4; ni++)
            #pragma unroll
            for (int r = 0; r < 4; r++) acc[mi][ni][r] = 0.f;

    const float* Wb = W + ((size_t)e * O + o0) * LD;
    int arow = (lane & 7) + ((lane >> 3) & 1) * 8;
    int acol = (lane >> 4) * 8;
    uint32_t aB0 = smem_u32(As) + (uint32_t)(((wo + arow) * AST + acol) * 2);
    uint32_t bB0 = smem_u32(Bs) + (uint32_t)(((wp + arow) * AST + acol) * 2);

    int rA = tid >> 4, c4 = tid & 15;
    const int S = I / 64;
    float4 ra[8], rb[4];

    {
        #pragma unroll
        for (int q = 0; q < 8; q++)
            ra[q] = *(const float4*)(Wb + (size_t)(rA + q * 16) * LD + c4 * 4);
        #pragma unroll
        for (int q = 0; q < 4; q++) {
            int pid = pids[rA + q * 16];
            int xr = SETX ? (pid >> 2) : pid;
            rb[q] = (pid >= 0) ? *(const float4*)(X + (size_t)xr * I + c4 * 4)
                               : make_float4(0.f, 0.f, 0.f, 0.f);
        }
    }

    for (int s = 0; s < S; s++) {
        int buf = s & 1;
        {
            __nv_bfloat16* ab = As + buf * 128 * AST;
            __nv_bfloat16* bb = Bs + buf * 64 * AST;
            #pragma unroll
            for (int q = 0; q < 8; q++) {
                __nv_bfloat162 h0 = __floats2bfloat162_rn(ra[q].x, ra[q].y);
                __nv_bfloat162 h1 = __floats2bfloat162_rn(ra[q].z, ra[q].w);
                uint2 pk; pk.x = *(uint32_t*)&h0; pk.y = *(uint32_t*)&h1;
                *(uint2*)(ab + (rA + q * 16) * AST + c4 * 4) = pk;
            }
            #pragma unroll
            for (int q = 0; q < 4; q++) {
                __nv_bfloat162 h0 = __floats2bfloat162_rn(rb[q].x, rb[q].y);
                __nv_bfloat162 h1 = __floats2bfloat162_rn(rb[q].z, rb[q].w);
                uint2 pk; pk.x = *(uint32_t*)&h0; pk.y = *(uint32_t*)&h1;
                *(uint2*)(bb + (rA + q * 16) * AST + c4 * 4) = pk;
            }
        }
        if (s + 1 < S) {
            int kc = (s + 1) * 64;
            #pragma unroll
            for (int q = 0; q < 8; q++)
                ra[q] = *(const float4*)(Wb + (size_t)(rA + q * 16) * LD + kc + c4 * 4);
            #pragma unroll
            for (int q = 0; q < 4; q++) {
                int pid = pids[rA + q * 16];
                int xr = SETX ? (pid >> 2) : pid;
                rb[q] = (pid >= 0) ? *(const float4*)(X + (size_t)xr * I + kc + c4 * 4)
                                   : make_float4(0.f, 0.f, 0.f, 0.f);
            }
        }
        __syncthreads();
        uint32_t aAddr = aB0 + (uint32_t)(buf * 128 * AST * 2);
        uint32_t bAddr = bB0 + (uint32_t)(buf * 64 * AST * 2);
        #pragma unroll
        for (int kk = 0; kk < 4; kk++) {
            uint32_t a0[4], a1[4], b0[4], b1[4];
            ldsm4(a0, aAddr + kk * 32);
            ldsm4(a1, aAddr + 16 * AST * 2 + kk * 32);
            ldsm4(b0, bAddr + kk * 32);
            ldsm4(b1, bAddr + 16 * AST * 2 + kk * 32);
            mma16816(acc[0][0], a0, b0[0], b0[2]);
            mma16816(acc[0][1], a0, b0[1], b0[3]);
            mma16816(acc[0][2], a0, b1[0], b1[2]);
            mma16816(acc[0][3], a0, b1[1], b1[3]);
            mma16816(acc[1][0], a1, b0[0], b0[2]);
            mma16816(acc[1][1], a1, b0[1], b0[3]);
            mma16816(acc[1][2], a1, b1[0], b1[2]);
            mma16816(acc[1][3], a1, b1[1], b1[3]);
        }
    }

    int grp = lane >> 2, tq = lane & 3;
    #pragma unroll
    for (int mi = 0; mi < 2; mi++) {
        int ob = o0 + wo + mi * 16 + grp;
        float bP0 = bP[e * O + ob];
        float bP8 = bP[e * O + ob + 8];
        float bG0 = 0.f, bG8 = 0.f;
        if (SETX) { bG0 = bG[e * O + ob]; bG8 = bG[e * O + ob + 8]; }
        #pragma unroll
        for (int ni = 0; ni < 4; ni++) {
            int pc = wp + ni * 8 + tq * 2;
            int pidA = pids[pc], pidB = pids[pc + 1];
            float* ac = acc[mi][ni];
            if (pidA >= 0) {
                bool pr = !SETX || (pidA < BP * KTOP);
                float b0s = pr ? bP0 : bG0, b8s = pr ? bP8 : bG8;
                float v0 = ac[0] + b0s; v0 = v0 > 0.f ? v0 : 0.01f * v0;
                float v2 = ac[2] + b8s; v2 = v2 > 0.f ? v2 : 0.01f * v2;
                Y[(size_t)pidA * O + ob] = v0;
                Y[(size_t)pidA * O + ob + 8] = v2;
            }
            if (pidB >= 0) {
                bool pr = !SETX || (pidB < BP * KTOP);
                float b0s = pr ? bP0 : bG0, b8s = pr ? bP8 : bG8;
                float v1 = ac[1] + b0s; v1 = v1 > 0.f ? v1 : 0.01f * v1;
                float v3 = ac[3] + b8s; v3 = v3 > 0.f ? v3 : 0.01f * v3;
                Y[(size_t)pidB * O + ob] = v1;
                Y[(size_t)pidB * O + ob + 8] = v3;
            }
        }
    }
}
#define SMEM_MLP ((2 * 128 + 2 * 64) * AST * 2)

// ------------------ fold probe_W into ctx (probe pairs only) ------------------
__global__ void k_ctx2gemm(const float* __restrict__ probeW) {
    __shared__ __align__(16) float Asm[16][68];
    __shared__ __align__(16) float Bsm[16][68];
    int p0 = blockIdx.x * 64;
    int e0 = blockIdx.y * 64;
    int tid = threadIdx.x;
    int ty = tid >> 4, tx = tid & 15;
    float acc[4][4];
    #pragma unroll
    for (int i = 0; i < 4; i++)
        #pragma unroll
        for (int j = 0; j < 4; j++) acc[i][j] = 0.f;
    for (int kc = 0; kc < D; kc += 16) {
        #pragma unroll
        for (int q = 0; q < 4; q++) {
            int lin = tid + q * 256;
            int r = lin >> 4, c = lin & 15;
            Asm[c][r] = g_ctxv[(size_t)(p0 + r) * D + kc + c];
        }
        #pragma unroll
        for (int q = 0; q < 4; q++) {
            int lin = tid + q * 256;
            int c = lin >> 6, ee = lin & 63;
            Bsm[c][ee] = probeW[(size_t)(kc + c) * D + e0 + ee];
        }
        __syncthreads();
        #pragma unroll
        for (int c = 0; c < 16; c++) {
            float4 av = *reinterpret_cast<const float4*>(&Asm[c][ty * 4]);
            float4 bv = *reinterpret_cast<const float4*>(&Bsm[c][tx * 4]);
            float a4[4] = {av.x, av.y, av.z, av.w};
            float b4[4] = {bv.x, bv.y, bv.z, bv.w};
            #pragma unroll
            for (int i = 0; i < 4; i++)
                #pragma unroll
                for (int j = 0; j < 4; j++) acc[i][j] += a4[i] * b4[j];
        }
        __syncthreads();
    }
    #pragma unroll
    for (int i = 0; i < 4; i++)
        #pragma unroll
        for (int j = 0; j < 4; j++)
            g_ctx2[(size_t)(p0 + ty * 4 + i) * D + e0 + tx * 4 + j] = acc[i][j];
}

// ------------------ chunked scores (inline cb for probes) ------------------
__global__ void __launch_bounds__(256) k_scores(
        const float* __restrict__ probes, const float* __restrict__ gallery,
        const int* __restrict__ plen, const int* __restrict__ glen,
        const float* __restrict__ probeB) {
    __shared__ float sCtx[KTOP * D];
    __shared__ float sCb[KTOP];
    int s = blockIdx.x, ch = blockIdx.y, tid = threadIdx.x;
    bool isP = s < BP;
    int L = isP ? LPROBE : LGAL;
    const float* feat = isP ? probes + (size_t)s * LPROBE * D
                            : gallery + (size_t)(s - BP) * LGAL * D;
    int len = isP ? plen[s] : glen[s - BP];
    len = max(1, min(len, L));
    int cl = L >> 3;
    int r0 = ch * cl, r1 = min(len, r0 + cl);
    if (r0 >= r1) return;
    const float* ctxsrc = isP ? g_ctx2 : g_ctxv;
    for (int i = tid; i < KTOP * D; i += 256) sCtx[i] = ctxsrc[(size_t)s * KTOP * D + i];
    if (tid < KTOP) sCb[tid] = 0.f;
    __syncthreads();
    int w = tid >> 5, lane = tid & 31;
    if (isP && w < KTOP) {
        float a = 0.f;
        const float* cv = g_ctxv + ((size_t)s * KTOP + w) * D;
        #pragma unroll
        for (int i = 0; i < 16; i++) {
            int col = lane + i * 32;
            a += probeB[col] * cv[col];
        }
        a = wredsum(a);
        if (lane == 0) sCb[w] = a;
    }
    __syncthreads();
    for (int base = r0 + w * 4; base < r1; base += 32) {
        float dd[4][KTOP], ss[4];
        #pragma unroll
        for (int q = 0; q < 4; q++) {
            ss[q] = 0.f;
            #pragma unroll
            for (int k = 0; k < KTOP; k++) dd[q][k] = 0.f;
        }
        const float* row0 = feat + (size_t)base * D;
        bool v1 = base + 1 < r1, v2 = base + 2 < r1, v3 = base + 3 < r1;
        #pragma unroll 4
        for (int ci = 0; ci < 16; ci++) {
            int col = lane + ci * 32;
            float x0 = row0[col];
            float x1 = v1 ? row0[D + col] : 0.f;
            float x2 = v2 ? row0[2 * D + col] : 0.f;
            float x3 = v3 ? row0[3 * D + col] : 0.f;
            ss[0] += x0 * x0; ss[1] += x1 * x1; ss[2] += x2 * x2; ss[3] += x3 * x3;
            #pragma unroll
            for (int k = 0; k < KTOP; k++) {
                float c = sCtx[k * D + col];
                dd[0][k] += x0 * c;
                dd[1][k] += x1 * c;
                dd[2][k] += x2 * c;
                dd[3][k] += x3 * c;
            }
        }
        #pragma unroll
        for (int q = 0; q < 4; q++) {
            if (base + q < r1) {
                float sv = wredsum(ss[q]);
                float d0 = wredsum(dd[q][0]);
                float d1 = wredsum(dd[q][1]);
                float d2 = wredsum(dd[q][2]);
                float d3 = wredsum(dd[q][3]);
                if (lane == 0) {
                    int l = base + q;
                    g_rn[s * LGAL + l] = 1.f / fmaxf(sqrtf(sv), 1e-12f);
                    size_t b = (size_t)(s * LGAL + l) * KTOP;
                    g_sc[b + 0] = d0 + sCb[0];
                    g_sc[b + 1] = d1 + sCb[1];
                    g_sc[b + 2] = d2 + sCb[2];
                    g_sc[b + 3] = d3 + sCb[3];
                }
            }
        }
    }
}

// ------------------ pooling accumulation with inline softmax ------------------
__global__ void __launch_bounds__(256) k_poolacc(
        const float* __restrict__ probes, const float* __restrict__ gallery,
        const int* __restrict__ plen, const int* __restrict__ glen) {
    __shared__ float sCo[64 * KTOP];
    __shared__ float sM[KTOP], sDen[KTOP];
    int s = blockIdx.x, ch = blockIdx.y, tid = threadIdx.x;
    bool isP = s < BP;
    int L = isP ? LPROBE : LGAL;
    const float* feat = isP ? probes + (size_t)s * LPROBE * D
                            : gallery + (size_t)(s - BP) * LGAL * D;
    int len = isP ? plen[s] : glen[s - BP];
    len = max(1, min(len, L));
    int cl = L >> 3;
    int r0 = ch * cl, r1 = min(len, r0 + cl);
    int nr = max(0, r1 - r0);

    {
        int w = tid >> 5, lane = tid & 31;
        if (w < KTOP) {
            float m = -3.4e38f;
            for (int l = lane; l < len; l += 32)
                m = fmaxf(m, g_sc[(size_t)(s * LGAL + l) * KTOP + w]);
            m = wredmax(m);
            float den = 0.f;
            for (int l = lane; l < len; l += 32)
                den += expf(g_sc[(size_t)(s * LGAL + l) * KTOP + w] - m);
            den = wredsum(den);
            if (lane == 0) { sM[w] = m; sDen[w] = den; }
        }
    }
    __syncthreads();
    for (int i = tid; i < nr * KTOP; i += 256) {
        int l = r0 + (i >> 2), k = i & 3;
        sCo[i] = expf(g_sc[(size_t)(s * LGAL + l) * KTOP + k] - sM[k]) / sDen[k]
               * g_rn[s * LGAL + l];
    }
    __syncthreads();

    int half = tid >> 7, cg = tid & 127;
    int col = cg * 4;
    float acc[KTOP][4];
    #pragma unroll
    for (int k = 0; k < KTOP; k++)
        #pragma unroll
        for (int c = 0; c < 4; c++) acc[k][c] = 0.f;

    for (int l = r0 + half; l < r1; l += 2) {
        float4 x = *(const float4*)(feat + (size_t)l * D + col);
        int lo = (l - r0) * KTOP;
        float c0 = sCo[lo + 0], c1 = sCo[lo + 1], c2 = sCo[lo + 2], c3 = sCo[lo + 3];
        acc[0][0] += x.x * c0; acc[0][1] += x.y * c0; acc[0][2] += x.z * c0; acc[0][3] += x.w * c0;
        acc[1][0] += x.x * c1; acc[1][1] += x.y * c1; acc[1][2] += x.z * c1; acc[1][3] += x.w * c1;
        acc[2][0] += x.x * c2; acc[2][1] += x.y * c2; acc[2][2] += x.z * c2; acc[2][3] += x.w * c2;
        acc[3][0] += x.x * c3; acc[3][1] += x.y * c3; acc[3][2] += x.z * c3; acc[3][3] += x.w * c3;
    }
    size_t pb = (size_t)((s * NCH + ch) * 2 + half) * KTOP;
    #pragma unroll
    for (int k = 0; k < KTOP; k++)
        *(float4*)(&g_pp[(pb + k) * D + col]) = make_float4(acc[k][0], acc[k][1], acc[k][2], acc[k][3]);
}

__global__ void k_poolred(float* __restrict__ out) {
    int s = blockIdx.x, tid = threadIdx.x;
    bool isP = s < BP;
    size_t ob = isP ? (OFF_FP + (size_t)s * KTOP * D)
                    : (OFF_FG + (size_t)(s - BP) * KTOP * D);
    #pragma unroll
    for (int k = 0; k < KTOP; k++) {
        #pragma unroll
        for (int h = 0; h < 2; h++) {
            int d = tid + h * 256;
            float v = 0.f;
            #pragma unroll
            for (int c = 0; c < NCH * 2; c++)
                v += g_pp[((size_t)(s * NCH * 2 + c) * KTOP + k) * D + d];
            out[ob + k * D + d] = v;
        }
    }
}

// ------------------ launch ------------------
extern "C" void kernel_launch(void* const* d_in, const int* in_sizes, int n_in,
                              void* d_out, int out_size) {
    const float* probes  = (const float*)d_in[0];
    const float* gallery = (const float*)d_in[1];
    const int*   plen    = (const int*)d_in[2];
    const int*   glen    = (const int*)d_in[3];
    const float* proxP   = (const float*)d_in[4];
    const float* proxG   = (const float*)d_in[5];
    const float* tW      = (const float*)d_in[6];
    const float* tb      = (const float*)d_in[7];
    const float* probeW  = (const float*)d_in[8];
    const float* probeB  = (const float*)d_in[9];
    const float* W1      = (const float*)d_in[10];
    const float* b1      = (const float*)d_in[11];
    const float* W2      = (const float*)d_in[12];
    const float* b2      = (const float*)d_in[13];
    const float* W3      = (const float*)d_in[14];
    const float* b3      = (const float*)d_in[15];
    float* out = (float*)d_out;

    float *h1, *h2, *ctxv, *sum, *pbP, *pbG;
    cudaGetSymbolAddress((void**)&h1, g_h1);
    cudaGetSymbolAddress((void**)&h2, g_h2);
    cudaGetSymbolAddress((void**)&ctxv, g_ctxv);
    cudaGetSymbolAddress((void**)&sum, g_sum);
    cudaGetSymbolAddress((void**)&pbP, g_pbP);
    cudaGetSymbolAddress((void**)&pbG, g_pbG);

    cudaFuncSetAttribute(k_mlp_t<1024, 1024, 1536, true>,  cudaFuncAttributeMaxDynamicSharedMemorySize, SMEM_MLP);
    cudaFuncSetAttribute(k_mlp_t<1024, 1024, 1024, false>, cudaFuncAttributeMaxDynamicSharedMemorySize, SMEM_MLP);
    cudaFuncSetAttribute(k_mlp_t<1024,  512, 1024, false>, cudaFuncAttributeMaxDynamicSharedMemorySize, SMEM_MLP);

    k_init<<<1, 256>>>(proxP, proxG, tW, tb, out);
    k_pbias<<<KALL, 256>>>(W1, b1, proxP, proxG);
    k_fuse1<<<dim3(NSET, NCH), 256>>>(probes, gallery, plen, glen, tW);
    k_prep<<<NSET, 256>>>(plen, glen);
    k_mlp_t<1024, 1024, 1536, true ><<<dim3(KALL, 8, 12), 256, SMEM_MLP>>>(W1, pbP, pbG, sum, h1);
    k_mlp_t<1024, 1024, 1024, false><<<dim3(KALL, 8, 12), 256, SMEM_MLP>>>(W2, b2, nullptr, h1, h2);
    k_mlp_t<1024,  512, 1024, false><<<dim3(KALL, 4, 12), 256, SMEM_MLP>>>(W3, b3, nullptr, h2, ctxv);
    k_ctx2gemm<<<dim3(8, 8), 256>>>(probeW);
    k_scores<<<dim3(NSET, NCH), 256>>>(probes, gallery, plen, glen, probeB);
    k_poolacc<<<dim3(NSET, NCH), 256>>>(probes, gallery, plen, glen);
    k_poolred<<<NSET, 256>>>(out);
}

// round 14
// speedup vs baseline: 2.3760x; 2.3760x over previous
#include <cuda_runtime.h>
#include <cuda_bf16.h>
#include <math.h>
#include <stdint.h>

#define D       512
#define KALL    11
#define KTOP    4
#define DOM     10
#define BP      128
#define LPROBE  256
#define BG      64
#define LGAL    512
#define NSET    192
#define NPAIR   768
#define NCH     8

#define OFF_FP  0
#define OFF_TP  262144
#define OFF_FG  262254
#define OFF_TG  393326

// ------------------ scratch ------------------
__device__ float g_tp[2 * KALL * DOM];
__device__ float g_ps[NSET * NCH * D];
__device__ float g_pq[NSET * NCH * D];
__device__ float g_tpart[NSET * NCH * DOM];
__device__ int   g_cnt[KALL];
__device__ int   g_list[KALL * NPAIR];
__device__ float g_sum[NPAIR * 1536];
__device__ float g_h1[NPAIR * 1024];
__device__ float g_h2[NPAIR * 1024];
__device__ float g_ctxv[NPAIR * 512];
__device__ float g_ctx2[NPAIR * 512];
__device__ float g_sc[NSET * LGAL * KTOP];
__device__ float g_rn[NSET * LGAL];
__device__ float g_pp[NSET * NCH * 2 * KTOP * D];

__device__ __forceinline__ float wredsum(float v) {
    #pragma unroll
    for (int o = 16; o; o >>= 1) v += __shfl_xor_sync(0xffffffffu, v, o);
    return v;
}
__device__ __forceinline__ float wredmax(float v) {
    #pragma unroll
    for (int o = 16; o; o >>= 1) v = fmaxf(v, __shfl_xor_sync(0xffffffffu, v, o));
    return v;
}
__device__ __forceinline__ uint32_t smem_u32(const void* p) {
    uint32_t a;
    asm("{ .reg .u64 t; cvta.to.shared.u64 t, %1; cvt.u32.u64 %0, t; }" : "=r"(a) : "l"(p));
    return a;
}
__device__ __forceinline__ void ldsm4(uint32_t* r, uint32_t addr) {
    asm volatile("ldmatrix.sync.aligned.m8n8.x4.shared.b16 {%0,%1,%2,%3}, [%4];"
        : "=r"(r[0]), "=r"(r[1]), "=r"(r[2]), "=r"(r[3]) : "r"(addr));
}
__device__ __forceinline__ void mma16816(float* d, const uint32_t* a, uint32_t b0, uint32_t b1) {
    asm volatile("mma.sync.aligned.m16n8k16.row.col.f32.bf16.bf16.f32 "
        "{%0,%1,%2,%3}, {%4,%5,%6,%7}, {%8,%9}, {%0,%1,%2,%3};"
        : "+f"(d[0]), "+f"(d[1]), "+f"(d[2]), "+f"(d[3])
        : "r"(a[0]), "r"(a[1]), "r"(a[2]), "r"(a[3]), "r"(b0), "r"(b1));
}

// ------------------ init ------------------
__global__ void k_init(const float* __restrict__ proxP, const float* __restrict__ proxG,
                       const float* __restrict__ tW, const float* __restrict__ tb,
                       float* __restrict__ out) {
    __shared__ float tv[220];
    int tid = threadIdx.x;
    if (tid < KALL) g_cnt[tid] = 0;
    if (tid < 220) {
        int which = tid / 110;
        int rem = tid - which * 110;
        int k = rem / DOM, j = rem - k * DOM;
        const float* prox = which ? proxG : proxP;
        float acc = tb[j];
        for (int d = 0; d < D; d++) acc += prox[k * D + d] * tW[j * D + d];
        out[(which ? OFF_TG : OFF_TP) + k * DOM + j] = acc;
        tv[tid] = acc;
    }
    __syncthreads();
    if (tid < 220) {
        int base = (tid / DOM) * DOM;
        float nn = 0.f;
        #pragma unroll
        for (int j = 0; j < DOM; j++) nn += tv[base + j] * tv[base + j];
        float inv = 1.f / fmaxf(sqrtf(nn), 1e-12f);
        g_tp[tid] = tv[tid] * inv;
    }
}

// ------------------ fused colstats + transform ------------------
__global__ void __launch_bounds__(256) k_fuse1(
        const float* __restrict__ probes, const float* __restrict__ gallery,
        const int* __restrict__ plen, const int* __restrict__ glen,
        const float* __restrict__ tW) {
    __shared__ float sWt[DOM * D];
    __shared__ float wsum[8][DOM];
    int s = blockIdx.x, ch = blockIdx.y, tid = threadIdx.x;
    bool isP = s < BP;
    int L = isP ? LPROBE : LGAL;
    const float* feat = isP ? probes + (size_t)s * LPROBE * D
                            : gallery + (size_t)(s - BP) * LGAL * D;
    int len = isP ? plen[s] : glen[s - BP];
    len = max(1, min(len, L));
    int cl = L >> 3;
    int r0 = ch * cl, r1 = min(len, r0 + cl);

    for (int i = tid; i < DOM * D; i += 256) sWt[i] = tW[i];

    {
        int d0 = tid, d1 = tid + 256;
        float s0 = 0.f, q0 = 0.f, s1 = 0.f, q1 = 0.f;
        for (int l = r0; l < r1; l++) {
            float x0 = feat[(size_t)l * D + d0];
            float x1 = feat[(size_t)l * D + d1];
            s0 += x0; q0 += x0 * x0;
            s1 += x1; q1 += x1 * x1;
        }
        size_t b = (size_t)(s * NCH + ch) * D;
        g_ps[b + d0] = s0; g_ps[b + d1] = s1;
        g_pq[b + d0] = q0; g_pq[b + d1] = q1;
    }
    __syncthreads();

    int w = tid >> 5, lane = tid & 31;
    float wacc[DOM];
    #pragma unroll
    for (int j = 0; j < DOM; j++) wacc[j] = 0.f;
    for (int base = r0 + w * 4; base < r1; base += 32) {
        float p[4][DOM];
        #pragma unroll
        for (int q = 0; q < 4; q++)
            #pragma unroll
            for (int j = 0; j < DOM; j++) p[q][j] = 0.f;
        const float* row0 = feat + (size_t)base * D;
        bool v1 = base + 1 < r1, v2 = base + 2 < r1, v3 = base + 3 < r1;
        #pragma unroll 4
        for (int ci = 0; ci < 16; ci++) {
            int col = lane + ci * 32;
            float x0 = row0[col];
            float x1 = v1 ? row0[D + col] : 0.f;
            float x2 = v2 ? row0[2 * D + col] : 0.f;
            float x3 = v3 ? row0[3 * D + col] : 0.f;
            #pragma unroll
            for (int j = 0; j < DOM; j++) {
                float wv = sWt[j * D + col];
                p[0][j] += x0 * wv;
                p[1][j] += x1 * wv;
                p[2][j] += x2 * wv;
                p[3][j] += x3 * wv;
            }
        }
        #pragma unroll
        for (int q = 0; q < 4; q++) {
            if (base + q < r1) {
                float nn = 0.f;
                #pragma unroll
                for (int j = 0; j < DOM; j++) { p[q][j] = wredsum(p[q][j]); nn += p[q][j] * p[q][j]; }
                float inv = 1.f / fmaxf(sqrtf(nn), 1e-12f);
                #pragma unroll
                for (int j = 0; j < DOM; j++) wacc[j] += p[q][j] * inv;
            }
        }
    }
    if (lane == 0) {
        #pragma unroll
        for (int j = 0; j < DOM; j++) wsum[w][j] = wacc[j];
    }
    __syncthreads();
    if (tid < DOM) {
        float a = 0.f;
        #pragma unroll
        for (int ww = 0; ww < 8; ww++) a += wsum[ww][tid];
        g_tpart[(s * NCH + ch) * DOM + tid] = a;
    }
}

// ------------------ prep: stats reduce + routing + summaries ------------------
__global__ void __launch_bounds__(256) k_prep(
        const int* __restrict__ plen, const int* __restrict__ glen,
        const float* __restrict__ proxP, const float* __restrict__ proxG) {
    __shared__ float sMean[D], sVar[D];
    __shared__ int sIdx[KTOP];
    int s = blockIdx.x, tid = threadIdx.x;
    bool isP = s < BP;
    int L = isP ? LPROBE : LGAL;
    int len = isP ? plen[s] : glen[s - BP];
    len = max(1, min(len, L));
    float rl = 1.f / (float)len;
    #pragma unroll
    for (int h = 0; h < 2; h++) {
        int d = tid + h * 256;
        float sm = 0.f, sq = 0.f;
        #pragma unroll
        for (int ch = 0; ch < NCH; ch++) {
            size_t b = (size_t)(s * NCH + ch) * D + d;
            sm += g_ps[b]; sq += g_pq[b];
        }
        float m = sm * rl;
        sMean[d] = m;
        sVar[d] = sq * rl - m * m;
    }
    if (tid == 0) {
        float tv[DOM];
        #pragma unroll
        for (int j = 0; j < DOM; j++) {
            float a = 0.f;
            #pragma unroll
            for (int c = 0; c < NCH; c++) a += g_tpart[(s * NCH + c) * DOM + j];
            tv[j] = a;
        }
        const float* tp = g_tp + (isP ? 0 : KALL * DOM);
        float gs[KALL];
        for (int k = 0; k < KALL; k++) {
            float a = 0.f;
            #pragma unroll
            for (int j = 0; j < DOM; j++) a += tv[j] * tp[k * DOM + j];
            gs[k] = a;
        }
        bool used[KALL];
        for (int k = 0; k < KALL; k++) used[k] = false;
        for (int t = 0; t < KTOP; t++) {
            int best = -1; float bv = -3.4e38f;
            for (int k = 0; k < KALL; k++)
                if (!used[k] && gs[k] > bv) { bv = gs[k]; best = k; }
            used[best] = true;
            sIdx[t] = best;
            int pos = atomicAdd(&g_cnt[best], 1);
            g_list[best * NPAIR + pos] = s * KTOP + t;
        }
    }
    __syncthreads();
    const float* prox = isP ? proxP : proxG;
    for (int k = 0; k < KTOP; k++) {
        int e = sIdx[k];
        size_t base = (size_t)(s * KTOP + k) * 1536;
        for (int i = tid; i < D; i += 256) {
            g_sum[base + i]         = sMean[i];
            g_sum[base + D + i]     = sVar[i];
            g_sum[base + 2 * D + i] = prox[e * D + i];
        }
    }
}

// ------------------ pipelined mma.sync bf16 expert-batched MLP layer ------------------
// grid: (p-tile, o-tile, expert) — p fastest so W-sharing blocks co-schedule.
#define AST 72
template <int I, int O>
__global__ void __launch_bounds__(256) k_mlp_t(const float* __restrict__ W, const float* __restrict__ Bb,
                                               const float* __restrict__ X, float* __restrict__ Y) {
    extern __shared__ __align__(16) __nv_bfloat16 sm[];
    __shared__ int pids[64];
    int e = blockIdx.z, o0 = blockIdx.y * 128, p0 = blockIdx.x * 64;
    int n = g_cnt[e];
    if (p0 >= n) return;
    int tid = threadIdx.x, wid = tid >> 5, lane = tid & 31;
    if (tid < 64) pids[tid] = (p0 + tid < n) ? g_list[e * NPAIR + p0 + tid] : -1;
    __syncthreads();

    __nv_bfloat16* As = sm;
    __nv_bfloat16* Bs = sm + 2 * 128 * AST;

    int wo = (wid >> 1) * 32;
    int wp = (wid & 1) * 32;
    float acc[2][4][4];
    #pragma unroll
    for (int mi = 0; mi < 2; mi++)
        #pragma unroll
        for (int ni = 0; ni < 4; ni++)
            #pragma unroll
            for (int r = 0; r < 4; r++) acc[mi][ni][r] = 0.f;

    const float* Wb = W + ((size_t)e * O + o0) * I;
    int arow = (lane & 7) + ((lane >> 3) & 1) * 8;
    int acol = (lane >> 4) * 8;
    uint32_t aB0 = smem_u32(As) + (uint32_t)(((wo + arow) * AST + acol) * 2);
    uint32_t bB0 = smem_u32(Bs) + (uint32_t)(((wp + arow) * AST + acol) * 2);

    int rA = tid >> 4, c4 = tid & 15;
    const int S = I / 64;
    float4 ra[8], rb[4];

    {
        #pragma unroll
        for (int q = 0; q < 8; q++)
            ra[q] = *(const float4*)(Wb + (size_t)(rA + q * 16) * I + c4 * 4);
        #pragma unroll
        for (int q = 0; q < 4; q++) {
            int pid = pids[rA + q * 16];
            rb[q] = (pid >= 0) ? *(const float4*)(X + (size_t)pid * I + c4 * 4)
                               : make_float4(0.f, 0.f, 0.f, 0.f);
        }
    }

    for (int s = 0; s < S; s++) {
        int buf = s & 1;
        {
            __nv_bfloat16* ab = As + buf * 128 * AST;
            __nv_bfloat16* bb = Bs + buf * 64 * AST;
            #pragma unroll
            for (int q = 0; q < 8; q++) {
                __nv_bfloat162 h0 = __floats2bfloat162_rn(ra[q].x, ra[q].y);
                __nv_bfloat162 h1 = __floats2bfloat162_rn(ra[q].z, ra[q].w);
                uint2 pk; pk.x = *(uint32_t*)&h0; pk.y = *(uint32_t*)&h1;
                *(uint2*)(ab + (rA + q * 16) * AST + c4 * 4) = pk;
            }
            #pragma unroll
            for (int q = 0; q < 4; q++) {
                __nv_bfloat162 h0 = __floats2bfloat162_rn(rb[q].x, rb[q].y);
                __nv_bfloat162 h1 = __floats2bfloat162_rn(rb[q].z, rb[q].w);
                uint2 pk; pk.x = *(uint32_t*)&h0; pk.y = *(uint32_t*)&h1;
                *(uint2*)(bb + (rA + q * 16) * AST + c4 * 4) = pk;
            }
        }
        if (s + 1 < S) {
            int kc = (s + 1) * 64;
            #pragma unroll
            for (int q = 0; q < 8; q++)
                ra[q] = *(const float4*)(Wb + (size_t)(rA + q * 16) * I + kc + c4 * 4);
            #pragma unroll
            for (int q = 0; q < 4; q++) {
                int pid = pids[rA + q * 16];
                rb[q] = (pid >= 0) ? *(const float4*)(X + (size_t)pid * I + kc + c4 * 4)
                                   : make_float4(0.f, 0.f, 0.f, 0.f);
            }
        }
        __syncthreads();
        uint32_t aAddr = aB0 + (uint32_t)(buf * 128 * AST * 2);
        uint32_t bAddr = bB0 + (uint32_t)(buf * 64 * AST * 2);
        #pragma unroll
        for (int kk = 0; kk < 4; kk++) {
            uint32_t a0[4], a1[4], b0[4], b1[4];
            ldsm4(a0, aAddr + kk * 32);
            ldsm4(a1, aAddr + 16 * AST * 2 + kk * 32);
            ldsm4(b0, bAddr + kk * 32);
            ldsm4(b1, bAddr + 16 * AST * 2 + kk * 32);
            mma16816(acc[0][0], a0, b0[0], b0[2]);
            mma16816(acc[0][1], a0, b0[1], b0[3]);
            mma16816(acc[0][2], a0, b1[0], b1[2]);
            mma16816(acc[0][3], a0, b1[1], b1[3]);
            mma16816(acc[1][0], a1, b0[0], b0[2]);
            mma16816(acc[1][1], a1, b0[1], b0[3]);
            mma16816(acc[1][2], a1, b1[0], b1[2]);
            mma16816(acc[1][3], a1, b1[1], b1[3]);
        }
    }

    int grp = lane >> 2, tq = lane & 3;
    #pragma unroll
    for (int mi = 0; mi < 2; mi++) {
        int ob = o0 + wo + mi * 16 + grp;
        float bi0 = Bb[e * O + ob];
        float bi8 = Bb[e * O + ob + 8];
        #pragma unroll
        for (int ni = 0; ni < 4; ni++) {
            int pc = wp + ni * 8 + tq * 2;
            int pidA = pids[pc], pidB = pids[pc + 1];
            float* ac = acc[mi][ni];
            if (pidA >= 0) {
                float v0 = ac[0] + bi0; v0 = v0 > 0.f ? v0 : 0.01f * v0;
                float v2 = ac[2] + bi8; v2 = v2 > 0.f ? v2 : 0.01f * v2;
                Y[(size_t)pidA * O + ob] = v0;
                Y[(size_t)pidA * O + ob + 8] = v2;
            }
            if (pidB >= 0) {
                float v1 = ac[1] + bi0; v1 = v1 > 0.f ? v1 : 0.01f * v1;
                float v3 = ac[3] + bi8; v3 = v3 > 0.f ? v3 : 0.01f * v3;
                Y[(size_t)pidB * O + ob] = v1;
                Y[(size_t)pidB * O + ob + 8] = v3;
            }
        }
    }
}
#define SMEM_MLP ((2 * 128 + 2 * 64) * AST * 2)

// ------------------ fold probe_W into ctx (probe pairs only) ------------------
__global__ void k_ctx2gemm(const float* __restrict__ probeW) {
    __shared__ __align__(16) float Asm[16][68];
    __shared__ __align__(16) float Bsm[16][68];
    int p0 = blockIdx.x * 64;
    int e0 = blockIdx.y * 64;
    int tid = threadIdx.x;
    int ty = tid >> 4, tx = tid & 15;
    float acc[4][4];
    #pragma unroll
    for (int i = 0; i < 4; i++)
        #pragma unroll
        for (int j = 0; j < 4; j++) acc[i][j] = 0.f;
    for (int kc = 0; kc < D; kc += 16) {
        #pragma unroll
        for (int q = 0; q < 4; q++) {
            int lin = tid + q * 256;
            int r = lin >> 4, c = lin & 15;
            Asm[c][r] = g_ctxv[(size_t)(p0 + r) * D + kc + c];
        }
        #pragma unroll
        for (int q = 0; q < 4; q++) {
            int lin = tid + q * 256;
            int c = lin >> 6, ee = lin & 63;
            Bsm[c][ee] = probeW[(size_t)(kc + c) * D + e0 + ee];
        }
        __syncthreads();
        #pragma unroll
        for (int c = 0; c < 16; c++) {
            float4 av = *reinterpret_cast<const float4*>(&Asm[c][ty * 4]);
            float4 bv = *reinterpret_cast<const float4*>(&Bsm[c][tx * 4]);
            float a4[4] = {av.x, av.y, av.z, av.w};
            float b4[4] = {bv.x, bv.y, bv.z, bv.w};
            #pragma unroll
            for (int i = 0; i < 4; i++)
                #pragma unroll
                for (int j = 0; j < 4; j++) acc[i][j] += a4[i] * b4[j];
        }
        __syncthreads();
    }
    #pragma unroll
    for (int i = 0; i < 4; i++)
        #pragma unroll
        for (int j = 0; j < 4; j++)
            g_ctx2[(size_t)(p0 + ty * 4 + i) * D + e0 + tx * 4 + j] = acc[i][j];
}

// ------------------ chunked scores (inline cb for probes) ------------------
__global__ void __launch_bounds__(256) k_scores(
        const float* __restrict__ probes, const float* __restrict__ gallery,
        const int* __restrict__ plen, const int* __restrict__ glen,
        const float* __restrict__ probeB) {
    __shared__ float sCtx[KTOP * D];
    __shared__ float sCb[KTOP];
    int s = blockIdx.x, ch = blockIdx.y, tid = threadIdx.x;
    bool isP = s < BP;
    int L = isP ? LPROBE : LGAL;
    const float* feat = isP ? probes + (size_t)s * LPROBE * D
                            : gallery + (size_t)(s - BP) * LGAL * D;
    int len = isP ? plen[s] : glen[s - BP];
    len = max(1, min(len, L));
    int cl = L >> 3;
    int r0 = ch * cl, r1 = min(len, r0 + cl);
    if (r0 >= r1) return;
    const float* ctxsrc = isP ? g_ctx2 : g_ctxv;
    for (int i = tid; i < KTOP * D; i += 256) sCtx[i] = ctxsrc[(size_t)s * KTOP * D + i];
    if (tid < KTOP) sCb[tid] = 0.f;
    __syncthreads();
    int w = tid >> 5, lane = tid & 31;
    if (isP && w < KTOP) {
        float a = 0.f;
        const float* cv = g_ctxv + ((size_t)s * KTOP + w) * D;
        #pragma unroll
        for (int i = 0; i < 16; i++) {
            int col = lane + i * 32;
            a += probeB[col] * cv[col];
        }
        a = wredsum(a);
        if (lane == 0) sCb[w] = a;
    }
    __syncthreads();
    for (int base = r0 + w * 4; base < r1; base += 32) {
        float dd[4][KTOP], ss[4];
        #pragma unroll
        for (int q = 0; q < 4; q++) {
            ss[q] = 0.f;
            #pragma unroll
            for (int k = 0; k < KTOP; k++) dd[q][k] = 0.f;
        }
        const float* row0 = feat + (size_t)base * D;
        bool v1 = base + 1 < r1, v2 = base + 2 < r1, v3 = base + 3 < r1;
        #pragma unroll 4
        for (int ci = 0; ci < 16; ci++) {
            int col = lane + ci * 32;
            float x0 = row0[col];
            float x1 = v1 ? row0[D + col] : 0.f;
            float x2 = v2 ? row0[2 * D + col] : 0.f;
            float x3 = v3 ? row0[3 * D + col] : 0.f;
            ss[0] += x0 * x0; ss[1] += x1 * x1; ss[2] += x2 * x2; ss[3] += x3 * x3;
            #pragma unroll
            for (int k = 0; k < KTOP; k++) {
                float c = sCtx[k * D + col];
                dd[0][k] += x0 * c;
                dd[1][k] += x1 * c;
                dd[2][k] += x2 * c;
                dd[3][k] += x3 * c;
            }
        }
        #pragma unroll
        for (int q = 0; q < 4; q++) {
            if (base + q < r1) {
                float sv = wredsum(ss[q]);
                float d0 = wredsum(dd[q][0]);
                float d1 = wredsum(dd[q][1]);
                float d2 = wredsum(dd[q][2]);
                float d3 = wredsum(dd[q][3]);
                if (lane == 0) {
                    int l = base + q;
                    g_rn[s * LGAL + l] = 1.f / fmaxf(sqrtf(sv), 1e-12f);
                    size_t b = (size_t)(s * LGAL + l) * KTOP;
                    g_sc[b + 0] = d0 + sCb[0];
                    g_sc[b + 1] = d1 + sCb[1];
                    g_sc[b + 2] = d2 + sCb[2];
                    g_sc[b + 3] = d3 + sCb[3];
                }
            }
        }
    }
}

// ------------------ pooling accumulation with inline softmax ------------------
__global__ void __launch_bounds__(256) k_poolacc(
        const float* __restrict__ probes, const float* __restrict__ gallery,
        const int* __restrict__ plen, const int* __restrict__ glen) {
    __shared__ float sCo[64 * KTOP];
    __shared__ float sM[KTOP], sDen[KTOP];
    int s = blockIdx.x, ch = blockIdx.y, tid = threadIdx.x;
    bool isP = s < BP;
    int L = isP ? LPROBE : LGAL;
    const float* feat = isP ? probes + (size_t)s * LPROBE * D
                            : gallery + (size_t)(s - BP) * LGAL * D;
    int len = isP ? plen[s] : glen[s - BP];
    len = max(1, min(len, L));
    int cl = L >> 3;
    int r0 = ch * cl, r1 = min(len, r0 + cl);
    int nr = max(0, r1 - r0);

    {
        int w = tid >> 5, lane = tid & 31;
        if (w < KTOP) {
            float m = -3.4e38f;
            for (int l = lane; l < len; l += 32)
                m = fmaxf(m, g_sc[(size_t)(s * LGAL + l) * KTOP + w]);
            m = wredmax(m);
            float den = 0.f;
            for (int l = lane; l < len; l += 32)
                den += expf(g_sc[(size_t)(s * LGAL + l) * KTOP + w] - m);
            den = wredsum(den);
            if (lane == 0) { sM[w] = m; sDen[w] = den; }
        }
    }
    __syncthreads();
    for (int i = tid; i < nr * KTOP; i += 256) {
        int l = r0 + (i >> 2), k = i & 3;
        sCo[i] = expf(g_sc[(size_t)(s * LGAL + l) * KTOP + k] - sM[k]) / sDen[k]
               * g_rn[s * LGAL + l];
    }
    __syncthreads();

    int half = tid >> 7, cg = tid & 127;
    int col = cg * 4;
    float acc[KTOP][4];
    #pragma unroll
    for (int k = 0; k < KTOP; k++)
        #pragma unroll
        for (int c = 0; c < 4; c++) acc[k][c] = 0.f;

    for (int l = r0 + half; l < r1; l += 2) {
        float4 x = *(const float4*)(feat + (size_t)l * D + col);
        int lo = (l - r0) * KTOP;
        float c0 = sCo[lo + 0], c1 = sCo[lo + 1], c2 = sCo[lo + 2], c3 = sCo[lo + 3];
        acc[0][0] += x.x * c0; acc[0][1] += x.y * c0; acc[0][2] += x.z * c0; acc[0][3] += x.w * c0;
        acc[1][0] += x.x * c1; acc[1][1] += x.y * c1; acc[1][2] += x.z * c1; acc[1][3] += x.w * c1;
        acc[2][0] += x.x * c2; acc[2][1] += x.y * c2; acc[2][2] += x.z * c2; acc[2][3] += x.w * c2;
        acc[3][0] += x.x * c3; acc[3][1] += x.y * c3; acc[3][2] += x.z * c3; acc[3][3] += x.w * c3;
    }
    size_t pb = (size_t)((s * NCH + ch) * 2 + half) * KTOP;
    #pragma unroll
    for (int k = 0; k < KTOP; k++)
        *(float4*)(&g_pp[(pb + k) * D + col]) = make_float4(acc[k][0], acc[k][1], acc[k][2], acc[k][3]);
}

__global__ void k_poolred(float* __restrict__ out) {
    int s = blockIdx.x, tid = threadIdx.x;
    bool isP = s < BP;
    size_t ob = isP ? (OFF_FP + (size_t)s * KTOP * D)
                    : (OFF_FG + (size_t)(s - BP) * KTOP * D);
    #pragma unroll
    for (int k = 0; k < KTOP; k++) {
        #pragma unroll
        for (int h = 0; h < 2; h++) {
            int d = tid + h * 256;
            float v = 0.f;
            #pragma unroll
            for (int c = 0; c < NCH * 2; c++)
                v += g_pp[((size_t)(s * NCH * 2 + c) * KTOP + k) * D + d];
            out[ob + k * D + d] = v;
        }
    }
}

// ------------------ launch ------------------
extern "C" void kernel_launch(void* const* d_in, const int* in_sizes, int n_in,
                              void* d_out, int out_size) {
    const float* probes  = (const float*)d_in[0];
    const float* gallery = (const float*)d_in[1];
    const int*   plen    = (const int*)d_in[2];
    const int*   glen    = (const int*)d_in[3];
    const float* proxP   = (const float*)d_in[4];
    const float* proxG   = (const float*)d_in[5];
    const float* tW      = (const float*)d_in[6];
    const float* tb      = (const float*)d_in[7];
    const float* probeW  = (const float*)d_in[8];
    const float* probeB  = (const float*)d_in[9];
    const float* W1      = (const float*)d_in[10];
    const float* b1      = (const float*)d_in[11];
    const float* W2      = (const float*)d_in[12];
    const float* b2      = (const float*)d_in[13];
    const float* W3      = (const float*)d_in[14];
    const float* b3      = (const float*)d_in[15];
    float* out = (float*)d_out;

    float *h1, *h2, *ctxv, *sum;
    cudaGetSymbolAddress((void**)&h1, g_h1);
    cudaGetSymbolAddress((void**)&h2, g_h2);
    cudaGetSymbolAddress((void**)&ctxv, g_ctxv);
    cudaGetSymbolAddress((void**)&sum, g_sum);

    cudaFuncSetAttribute(k_mlp_t<1536, 1024>, cudaFuncAttributeMaxDynamicSharedMemorySize, SMEM_MLP);
    cudaFuncSetAttribute(k_mlp_t<1024, 1024>, cudaFuncAttributeMaxDynamicSharedMemorySize, SMEM_MLP);
    cudaFuncSetAttribute(k_mlp_t<1024,  512>, cudaFuncAttributeMaxDynamicSharedMemorySize, SMEM_MLP);

    k_init<<<1, 256>>>(proxP, proxG, tW, tb, out);
    k_fuse1<<<dim3(NSET, NCH), 256>>>(probes, gallery, plen, glen, tW);
    k_prep<<<NSET, 256>>>(plen, glen, proxP, proxG);
    k_mlp_t<1536, 1024><<<dim3(12, 8, KALL), 256, SMEM_MLP>>>(W1, b1, sum, h1);
    k_mlp_t<1024, 1024><<<dim3(12, 8, KALL), 256, SMEM_MLP>>>(W2, b2, h1, h2);
    k_mlp_t<1024,  512><<<dim3(12, 4, KALL), 256, SMEM_MLP>>>(W3, b3, h2, ctxv);
    k_ctx2gemm<<<dim3(8, 8), 256>>>(probeW);
    k_scores<<<dim3(NSET, NCH), 256>>>(probes, gallery, plen, glen, probeB);
    k_poolacc<<<dim3(NSET, NCH), 256>>>(probes, gallery, plen, glen);
    k_poolred<<<NSET, 256>>>(out);
}

// round 16
// speedup vs baseline: 2.5270x; 1.0636x over previous
#include <cuda_runtime.h>
#include <cuda_bf16.h>
#include <math.h>
#include <stdint.h>

#define D       512
#define KALL    11
#define KTOP    4
#define DOM     10
#define BP      128
#define LPROBE  256
#define BG      64
#define LGAL    512
#define NSET    192
#define NPAIR   768
#define NCH     8

#define OFF_FP  0
#define OFF_TP  262144
#define OFF_FG  262254
#define OFF_TG  393326

// ------------------ scratch ------------------
__device__ float g_tp[2 * KALL * DOM];
__device__ float g_ps[NSET * NCH * D];
__device__ float g_pq[NSET * NCH * D];
__device__ float g_tpart[NSET * NCH * DOM];
__device__ int   g_cnt[KALL];
__device__ int   g_list[KALL * NPAIR];
__device__ float g_sum[NPAIR * 1536];
__device__ float g_h1[NPAIR * 1024];
__device__ float g_h2[NPAIR * 1024];
__device__ float g_ctxv[NPAIR * 512];
__device__ float g_ctx2[NPAIR * 512];
__device__ float g_sc[NSET * LGAL * KTOP];
__device__ float g_rn[NSET * LGAL];
__device__ float g_pp[NSET * NCH * 2 * KTOP * D];

__device__ __forceinline__ float wredsum(float v) {
    #pragma unroll
    for (int o = 16; o; o >>= 1) v += __shfl_xor_sync(0xffffffffu, v, o);
    return v;
}
__device__ __forceinline__ float wredmax(float v) {
    #pragma unroll
    for (int o = 16; o; o >>= 1) v = fmaxf(v, __shfl_xor_sync(0xffffffffu, v, o));
    return v;
}
__device__ __forceinline__ uint32_t smem_u32(const void* p) {
    uint32_t a;
    asm("{ .reg .u64 t; cvta.to.shared.u64 t, %1; cvt.u32.u64 %0, t; }" : "=r"(a) : "l"(p));
    return a;
}
__device__ __forceinline__ void ldsm4(uint32_t* r, uint32_t addr) {
    asm volatile("ldmatrix.sync.aligned.m8n8.x4.shared.b16 {%0,%1,%2,%3}, [%4];"
        : "=r"(r[0]), "=r"(r[1]), "=r"(r[2]), "=r"(r[3]) : "r"(addr));
}
__device__ __forceinline__ void mma16816(float* d, const uint32_t* a, uint32_t b0, uint32_t b1) {
    asm volatile("mma.sync.aligned.m16n8k16.row.col.f32.bf16.bf16.f32 "
        "{%0,%1,%2,%3}, {%4,%5,%6,%7}, {%8,%9}, {%0,%1,%2,%3};"
        : "+f"(d[0]), "+f"(d[1]), "+f"(d[2]), "+f"(d[3])
        : "r"(a[0]), "r"(a[1]), "r"(a[2]), "r"(a[3]), "r"(b0), "r"(b1));
}

// ------------------ init ------------------
__global__ void k_init(const float* __restrict__ proxP, const float* __restrict__ proxG,
                       const float* __restrict__ tW, const float* __restrict__ tb,
                       float* __restrict__ out) {
    __shared__ float tv[220];
    int tid = threadIdx.x;
    if (tid < KALL) g_cnt[tid] = 0;
    if (tid < 220) {
        int which = tid / 110;
        int rem = tid - which * 110;
        int k = rem / DOM, j = rem - k * DOM;
        const float* prox = which ? proxG : proxP;
        float acc = tb[j];
        for (int d = 0; d < D; d++) acc += prox[k * D + d] * tW[j * D + d];
        out[(which ? OFF_TG : OFF_TP) + k * DOM + j] = acc;
        tv[tid] = acc;
    }
    __syncthreads();
    if (tid < 220) {
        int base = (tid / DOM) * DOM;
        float nn = 0.f;
        #pragma unroll
        for (int j = 0; j < DOM; j++) nn += tv[base + j] * tv[base + j];
        float inv = 1.f / fmaxf(sqrtf(nn), 1e-12f);
        g_tp[tid] = tv[tid] * inv;
    }
}

// ------------------ fused colstats + transform ------------------
__global__ void __launch_bounds__(256) k_fuse1(
        const float* __restrict__ probes, const float* __restrict__ gallery,
        const int* __restrict__ plen, const int* __restrict__ glen,
        const float* __restrict__ tW) {
    __shared__ float sWt[DOM * D];
    __shared__ float wsum[8][DOM];
    int s = blockIdx.x, ch = blockIdx.y, tid = threadIdx.x;
    bool isP = s < BP;
    int L = isP ? LPROBE : LGAL;
    const float* feat = isP ? probes + (size_t)s * LPROBE * D
                            : gallery + (size_t)(s - BP) * LGAL * D;
    int len = isP ? plen[s] : glen[s - BP];
    len = max(1, min(len, L));
    int cl = L >> 3;
    int r0 = ch * cl, r1 = min(len, r0 + cl);

    for (int i = tid; i < DOM * D; i += 256) sWt[i] = tW[i];

    {
        int d0 = tid, d1 = tid + 256;
        float s0 = 0.f, q0 = 0.f, s1 = 0.f, q1 = 0.f;
        for (int l = r0; l < r1; l++) {
            float x0 = feat[(size_t)l * D + d0];
            float x1 = feat[(size_t)l * D + d1];
            s0 += x0; q0 += x0 * x0;
            s1 += x1; q1 += x1 * x1;
        }
        size_t b = (size_t)(s * NCH + ch) * D;
        g_ps[b + d0] = s0; g_ps[b + d1] = s1;
        g_pq[b + d0] = q0; g_pq[b + d1] = q1;
    }
    __syncthreads();

    int w = tid >> 5, lane = tid & 31;
    float wacc[DOM];
    #pragma unroll
    for (int j = 0; j < DOM; j++) wacc[j] = 0.f;
    for (int base = r0 + w * 4; base < r1; base += 32) {
        float p[4][DOM];
        #pragma unroll
        for (int q = 0; q < 4; q++)
            #pragma unroll
            for (int j = 0; j < DOM; j++) p[q][j] = 0.f;
        const float* row0 = feat + (size_t)base * D;
        bool v1 = base + 1 < r1, v2 = base + 2 < r1, v3 = base + 3 < r1;
        #pragma unroll 4
        for (int ci = 0; ci < 16; ci++) {
            int col = lane + ci * 32;
            float x0 = row0[col];
            float x1 = v1 ? row0[D + col] : 0.f;
            float x2 = v2 ? row0[2 * D + col] : 0.f;
            float x3 = v3 ? row0[3 * D + col] : 0.f;
            #pragma unroll
            for (int j = 0; j < DOM; j++) {
                float wv = sWt[j * D + col];
                p[0][j] += x0 * wv;
                p[1][j] += x1 * wv;
                p[2][j] += x2 * wv;
                p[3][j] += x3 * wv;
            }
        }
        #pragma unroll
        for (int q = 0; q < 4; q++) {
            if (base + q < r1) {
                float nn = 0.f;
                #pragma unroll
                for (int j = 0; j < DOM; j++) { p[q][j] = wredsum(p[q][j]); nn += p[q][j] * p[q][j]; }
                float inv = 1.f / fmaxf(sqrtf(nn), 1e-12f);
                #pragma unroll
                for (int j = 0; j < DOM; j++) wacc[j] += p[q][j] * inv;
            }
        }
    }
    if (lane == 0) {
        #pragma unroll
        for (int j = 0; j < DOM; j++) wsum[w][j] = wacc[j];
    }
    __syncthreads();
    if (tid < DOM) {
        float a = 0.f;
        #pragma unroll
        for (int ww = 0; ww < 8; ww++) a += wsum[ww][tid];
        g_tpart[(s * NCH + ch) * DOM + tid] = a;
    }
}

// ------------------ prep: stats reduce + routing (warp-parallel) + summaries ------------------
__global__ void __launch_bounds__(256) k_prep(
        const int* __restrict__ plen, const int* __restrict__ glen,
        const float* __restrict__ proxP, const float* __restrict__ proxG) {
    __shared__ float sMean[D], sVar[D];
    __shared__ float sTv[DOM], sGs[KALL];
    __shared__ int sIdx[KTOP];
    int s = blockIdx.x, tid = threadIdx.x;
    bool isP = s < BP;
    int L = isP ? LPROBE : LGAL;
    int len = isP ? plen[s] : glen[s - BP];
    len = max(1, min(len, L));
    float rl = 1.f / (float)len;
    #pragma unroll
    for (int h = 0; h < 2; h++) {
        int d = tid + h * 256;
        float sm = 0.f, sq = 0.f;
        #pragma unroll
        for (int ch = 0; ch < NCH; ch++) {
            size_t b = (size_t)(s * NCH + ch) * D + d;
            sm += g_ps[b]; sq += g_pq[b];
        }
        float m = sm * rl;
        sMean[d] = m;
        sVar[d] = sq * rl - m * m;
    }
    int w = tid >> 5, lane = tid & 31;
    if (w == 0) {
        if (lane < DOM) {
            float a = 0.f;
            #pragma unroll
            for (int c = 0; c < NCH; c++) a += g_tpart[(s * NCH + c) * DOM + lane];
            sTv[lane] = a;
        }
        __syncwarp();
        if (lane < KALL) {
            const float* tp = g_tp + (isP ? 0 : KALL * DOM);
            float a = 0.f;
            #pragma unroll
            for (int j = 0; j < DOM; j++) a += sTv[j] * tp[lane * DOM + j];
            sGs[lane] = a;
        }
        __syncwarp();
        if (lane == 0) {
            bool used[KALL];
            for (int k = 0; k < KALL; k++) used[k] = false;
            for (int t = 0; t < KTOP; t++) {
                int best = -1; float bv = -3.4e38f;
                for (int k = 0; k < KALL; k++)
                    if (!used[k] && sGs[k] > bv) { bv = sGs[k]; best = k; }
                used[best] = true;
                sIdx[t] = best;
                int pos = atomicAdd(&g_cnt[best], 1);
                g_list[best * NPAIR + pos] = s * KTOP + t;
            }
        }
    }
    __syncthreads();
    const float* prox = isP ? proxP : proxG;
    for (int k = 0; k < KTOP; k++) {
        int e = sIdx[k];
        size_t base = (size_t)(s * KTOP + k) * 1536;
        for (int i = tid; i < D; i += 256) {
            g_sum[base + i]         = sMean[i];
            g_sum[base + D + i]     = sVar[i];
            g_sum[base + 2 * D + i] = prox[e * D + i];
        }
    }
}

// ------------------ pipelined mma.sync bf16 expert-batched MLP layer ------------------
#define AST 72
template <int I, int O>
__global__ void __launch_bounds__(256) k_mlp_t(const float* __restrict__ W, const float* __restrict__ Bb,
                                               const float* __restrict__ X, float* __restrict__ Y) {
    extern __shared__ __align__(16) __nv_bfloat16 sm[];
    __shared__ int pids[64];
    int e = blockIdx.x, o0 = blockIdx.y * 128, p0 = blockIdx.z * 64;
    int n = g_cnt[e];
    if (p0 >= n) return;
    int tid = threadIdx.x, wid = tid >> 5, lane = tid & 31;
    if (tid < 64) pids[tid] = (p0 + tid < n) ? g_list[e * NPAIR + p0 + tid] : -1;
    __syncthreads();

    __nv_bfloat16* As = sm;
    __nv_bfloat16* Bs = sm + 2 * 128 * AST;

    int wo = (wid >> 1) * 32;
    int wp = (wid & 1) * 32;
    float acc[2][4][4];
    #pragma unroll
    for (int mi = 0; mi < 2; mi++)
        #pragma unroll
        for (int ni = 0; ni < 4; ni++)
            #pragma unroll
            for (int r = 0; r < 4; r++) acc[mi][ni][r] = 0.f;

    const float* Wb = W + ((size_t)e * O + o0) * I;
    int arow = (lane & 7) + ((lane >> 3) & 1) * 8;
    int acol = (lane >> 4) * 8;
    uint32_t aB0 = smem_u32(As) + (uint32_t)(((wo + arow) * AST + acol) * 2);
    uint32_t bB0 = smem_u32(Bs) + (uint32_t)(((wp + arow) * AST + acol) * 2);

    int rA = tid >> 4, c4 = tid & 15;
    const int S = I / 64;
    float4 ra[8], rb[4];

    {
        #pragma unroll
        for (int q = 0; q < 8; q++)
            ra[q] = *(const float4*)(Wb + (size_t)(rA + q * 16) * I + c4 * 4);
        #pragma unroll
        for (int q = 0; q < 4; q++) {
            int pid = pids[rA + q * 16];
            rb[q] = (pid >= 0) ? *(const float4*)(X + (size_t)pid * I + c4 * 4)
                               : make_float4(0.f, 0.f, 0.f, 0.f);
        }
    }

    for (int s = 0; s < S; s++) {
        int buf = s & 1;
        {
            __nv_bfloat16* ab = As + buf * 128 * AST;
            __nv_bfloat16* bb = Bs + buf * 64 * AST;
            #pragma unroll
            for (int q = 0; q < 8; q++) {
                __nv_bfloat162 h0 = __floats2bfloat162_rn(ra[q].x, ra[q].y);
                __nv_bfloat162 h1 = __floats2bfloat162_rn(ra[q].z, ra[q].w);
                uint2 pk; pk.x = *(uint32_t*)&h0; pk.y = *(uint32_t*)&h1;
                *(uint2*)(ab + (rA + q * 16) * AST + c4 * 4) = pk;
            }
            #pragma unroll
            for (int q = 0; q < 4; q++) {
                __nv_bfloat162 h0 = __floats2bfloat162_rn(rb[q].x, rb[q].y);
                __nv_bfloat162 h1 = __floats2bfloat162_rn(rb[q].z, rb[q].w);
                uint2 pk; pk.x = *(uint32_t*)&h0; pk.y = *(uint32_t*)&h1;
                *(uint2*)(bb + (rA + q * 16) * AST + c4 * 4) = pk;
            }
        }
        if (s + 1 < S) {
            int kc = (s + 1) * 64;
            #pragma unroll
            for (int q = 0; q < 8; q++)
                ra[q] = *(const float4*)(Wb + (size_t)(rA + q * 16) * I + kc + c4 * 4);
            #pragma unroll
            for (int q = 0; q < 4; q++) {
                int pid = pids[rA + q * 16];
                rb[q] = (pid >= 0) ? *(const float4*)(X + (size_t)pid * I + kc + c4 * 4)
                                   : make_float4(0.f, 0.f, 0.f, 0.f);
            }
        }
        __syncthreads();
        uint32_t aAddr = aB0 + (uint32_t)(buf * 128 * AST * 2);
        uint32_t bAddr = bB0 + (uint32_t)(buf * 64 * AST * 2);
        #pragma unroll
        for (int kk = 0; kk < 4; kk++) {
            uint32_t a0[4], a1[4], b0[4], b1[4];
            ldsm4(a0, aAddr + kk * 32);
            ldsm4(a1, aAddr + 16 * AST * 2 + kk * 32);
            ldsm4(b0, bAddr + kk * 32);
            ldsm4(b1, bAddr + 16 * AST * 2 + kk * 32);
            mma16816(acc[0][0], a0, b0[0], b0[2]);
            mma16816(acc[0][1], a0, b0[1], b0[3]);
            mma16816(acc[0][2], a0, b1[0], b1[2]);
            mma16816(acc[0][3], a0, b1[1], b1[3]);
            mma16816(acc[1][0], a1, b0[0], b0[2]);
            mma16816(acc[1][1], a1, b0[1], b0[3]);
            mma16816(acc[1][2], a1, b1[0], b1[2]);
            mma16816(acc[1][3], a1, b1[1], b1[3]);
        }
    }

    int grp = lane >> 2, tq = lane & 3;
    #pragma unroll
    for (int mi = 0; mi < 2; mi++) {
        int ob = o0 + wo + mi * 16 + grp;
        float bi0 = Bb[e * O + ob];
        float bi8 = Bb[e * O + ob + 8];
        #pragma unroll
        for (int ni = 0; ni < 4; ni++) {
            int pc = wp + ni * 8 + tq * 2;
            int pidA = pids[pc], pidB = pids[pc + 1];
            float* ac = acc[mi][ni];
            if (pidA >= 0) {
                float v0 = ac[0] + bi0; v0 = v0 > 0.f ? v0 : 0.01f * v0;
                float v2 = ac[2] + bi8; v2 = v2 > 0.f ? v2 : 0.01f * v2;
                Y[(size_t)pidA * O + ob] = v0;
                Y[(size_t)pidA * O + ob + 8] = v2;
            }
            if (pidB >= 0) {
                float v1 = ac[1] + bi0; v1 = v1 > 0.f ? v1 : 0.01f * v1;
                float v3 = ac[3] + bi8; v3 = v3 > 0.f ? v3 : 0.01f * v3;
                Y[(size_t)pidB * O + ob] = v1;
                Y[(size_t)pidB * O + ob + 8] = v3;
            }
        }
    }
}
#define SMEM_MLP ((2 * 128 + 2 * 64) * AST * 2)

// ------------------ fold probe_W into ctx (probe pairs only) ------------------
__global__ void k_ctx2gemm(const float* __restrict__ probeW) {
    __shared__ __align__(16) float Asm[16][68];
    __shared__ __align__(16) float Bsm[16][68];
    int p0 = blockIdx.x * 64;
    int e0 = blockIdx.y * 64;
    int tid = threadIdx.x;
    int ty = tid >> 4, tx = tid & 15;
    float acc[4][4];
    #pragma unroll
    for (int i = 0; i < 4; i++)
        #pragma unroll
        for (int j = 0; j < 4; j++) acc[i][j] = 0.f;
    for (int kc = 0; kc < D; kc += 16) {
        #pragma unroll
        for (int q = 0; q < 4; q++) {
            int lin = tid + q * 256;
            int r = lin >> 4, c = lin & 15;
            Asm[c][r] = g_ctxv[(size_t)(p0 + r) * D + kc + c];
        }
        #pragma unroll
        for (int q = 0; q < 4; q++) {
            int lin = tid + q * 256;
            int c = lin >> 6, ee = lin & 63;
            Bsm[c][ee] = probeW[(size_t)(kc + c) * D + e0 + ee];
        }
        __syncthreads();
        #pragma unroll
        for (int c = 0; c < 16; c++) {
            float4 av = *reinterpret_cast<const float4*>(&Asm[c][ty * 4]);
            float4 bv = *reinterpret_cast<const float4*>(&Bsm[c][tx * 4]);
            float a4[4] = {av.x, av.y, av.z, av.w};
            float b4[4] = {bv.x, bv.y, bv.z, bv.w};
            #pragma unroll
            for (int i = 0; i < 4; i++)
                #pragma unroll
                for (int j = 0; j < 4; j++) acc[i][j] += a4[i] * b4[j];
        }
        __syncthreads();
    }
    #pragma unroll
    for (int i = 0; i < 4; i++)
        #pragma unroll
        for (int j = 0; j < 4; j++)
            g_ctx2[(size_t)(p0 + ty * 4 + i) * D + e0 + tx * 4 + j] = acc[i][j];
}

// ------------------ chunked scores (inline cb for probes) ------------------
__global__ void __launch_bounds__(256) k_scores(
        const float* __restrict__ probes, const float* __restrict__ gallery,
        const int* __restrict__ plen, const int* __restrict__ glen,
        const float* __restrict__ probeB) {
    __shared__ float sCtx[KTOP * D];
    __shared__ float sCb[KTOP];
    int s = blockIdx.x, ch = blockIdx.y, tid = threadIdx.x;
    bool isP = s < BP;
    int L = isP ? LPROBE : LGAL;
    const float* feat = isP ? probes + (size_t)s * LPROBE * D
                            : gallery + (size_t)(s - BP) * LGAL * D;
    int len = isP ? plen[s] : glen[s - BP];
    len = max(1, min(len, L));
    int cl = L >> 3;
    int r0 = ch * cl, r1 = min(len, r0 + cl);
    if (r0 >= r1) return;
    const float* ctxsrc = isP ? g_ctx2 : g_ctxv;
    for (int i = tid; i < KTOP * D; i += 256) sCtx[i] = ctxsrc[(size_t)s * KTOP * D + i];
    if (tid < KTOP) sCb[tid] = 0.f;
    __syncthreads();
    int w = tid >> 5, lane = tid & 31;
    if (isP && w < KTOP) {
        float a = 0.f;
        const float* cv = g_ctxv + ((size_t)s * KTOP + w) * D;
        #pragma unroll
        for (int i = 0; i < 16; i++) {
            int col = lane + i * 32;
            a += probeB[col] * cv[col];
        }
        a = wredsum(a);
        if (lane == 0) sCb[w] = a;
    }
    __syncthreads();
    for (int base = r0 + w * 4; base < r1; base += 32) {
        float dd[4][KTOP], ss[4];
        #pragma unroll
        for (int q = 0; q < 4; q++) {
            ss[q] = 0.f;
            #pragma unroll
            for (int k = 0; k < KTOP; k++) dd[q][k] = 0.f;
        }
        const float* row0 = feat + (size_t)base * D;
        bool v1 = base + 1 < r1, v2 = base + 2 < r1, v3 = base + 3 < r1;
        #pragma unroll 4
        for (int ci = 0; ci < 16; ci++) {
            int col = lane + ci * 32;
            float x0 = row0[col];
            float x1 = v1 ? row0[D + col] : 0.f;
            float x2 = v2 ? row0[2 * D + col] : 0.f;
            float x3 = v3 ? row0[3 * D + col] : 0.f;
            ss[0] += x0 * x0; ss[1] += x1 * x1; ss[2] += x2 * x2; ss[3] += x3 * x3;
            #pragma unroll
            for (int k = 0; k < KTOP; k++) {
                float c = sCtx[k * D + col];
                dd[0][k] += x0 * c;
                dd[1][k] += x1 * c;
                dd[2][k] += x2 * c;
                dd[3][k] += x3 * c;
            }
        }
        #pragma unroll
        for (int q = 0; q < 4; q++) {
            if (base + q < r1) {
                float sv = wredsum(ss[q]);
                float d0 = wredsum(dd[q][0]);
                float d1 = wredsum(dd[q][1]);
                float d2 = wredsum(dd[q][2]);
                float d3 = wredsum(dd[q][3]);
                if (lane == 0) {
                    int l = base + q;
                    g_rn[s * LGAL + l] = 1.f / fmaxf(sqrtf(sv), 1e-12f);
                    size_t b = (size_t)(s * LGAL + l) * KTOP;
                    g_sc[b + 0] = d0 + sCb[0];
                    g_sc[b + 1] = d1 + sCb[1];
                    g_sc[b + 2] = d2 + sCb[2];
                    g_sc[b + 3] = d3 + sCb[3];
                }
            }
        }
    }
}

// ------------------ pooling accumulation with inline softmax ------------------
__global__ void __launch_bounds__(256) k_poolacc(
        const float* __restrict__ probes, const float* __restrict__ gallery,
        const int* __restrict__ plen, const int* __restrict__ glen) {
    __shared__ float sCo[64 * KTOP];
    __shared__ float sM[KTOP], sDen[KTOP];
    int s = blockIdx.x, ch = blockIdx.y, tid = threadIdx.x;
    bool isP = s < BP;
    int L = isP ? LPROBE : LGAL;
    const float* feat = isP ? probes + (size_t)s * LPROBE * D
                            : gallery + (size_t)(s - BP) * LGAL * D;
    int len = isP ? plen[s] : glen[s - BP];
    len = max(1, min(len, L));
    int cl = L >> 3;
    int r0 = ch * cl, r1 = min(len, r0 + cl);
    int nr = max(0, r1 - r0);

    {
        int w = tid >> 5, lane = tid & 31;
        if (w < KTOP) {
            float m = -3.4e38f;
            for (int l = lane; l < len; l += 32)
                m = fmaxf(m, g_sc[(size_t)(s * LGAL + l) * KTOP + w]);
            m = wredmax(m);
            float den = 0.f;
            for (int l = lane; l < len; l += 32)
                den += expf(g_sc[(size_t)(s * LGAL + l) * KTOP + w] - m);
            den = wredsum(den);
            if (lane == 0) { sM[w] = m; sDen[w] = den; }
        }
    }
    __syncthreads();
    for (int i = tid; i < nr * KTOP; i += 256) {
        int l = r0 + (i >> 2), k = i & 3;
        sCo[i] = expf(g_sc[(size_t)(s * LGAL + l) * KTOP + k] - sM[k]) / sDen[k]
               * g_rn[s * LGAL + l];
    }
    __syncthreads();

    int half = tid >> 7, cg = tid & 127;
    int col = cg * 4;
    float acc[KTOP][4];
    #pragma unroll
    for (int k = 0; k < KTOP; k++)
        #pragma unroll
        for (int c = 0; c < 4; c++) acc[k][c] = 0.f;

    for (int l = r0 + half; l < r1; l += 2) {
        float4 x = *(const float4*)(feat + (size_t)l * D + col);
        int lo = (l - r0) * KTOP;
        float c0 = sCo[lo + 0], c1 = sCo[lo + 1], c2 = sCo[lo + 2], c3 = sCo[lo + 3];
        acc[0][0] += x.x * c0; acc[0][1] += x.y * c0; acc[0][2] += x.z * c0; acc[0][3] += x.w * c0;
        acc[1][0] += x.x * c1; acc[1][1] += x.y * c1; acc[1][2] += x.z * c1; acc[1][3] += x.w * c1;
        acc[2][0] += x.x * c2; acc[2][1] += x.y * c2; acc[2][2] += x.z * c2; acc[2][3] += x.w * c2;
        acc[3][0] += x.x * c3; acc[3][1] += x.y * c3; acc[3][2] += x.z * c3; acc[3][3] += x.w * c3;
    }
    size_t pb = (size_t)((s * NCH + ch) * 2 + half) * KTOP;
    #pragma unroll
    for (int k = 0; k < KTOP; k++)
        *(float4*)(&g_pp[(pb + k) * D + col]) = make_float4(acc[k][0], acc[k][1], acc[k][2], acc[k][3]);
}

__global__ void k_poolred(float* __restrict__ out) {
    int s = blockIdx.x, tid = threadIdx.x;
    bool isP = s < BP;
    size_t ob = isP ? (OFF_FP + (size_t)s * KTOP * D)
                    : (OFF_FG + (size_t)(s - BP) * KTOP * D);
    #pragma unroll
    for (int k = 0; k < KTOP; k++) {
        #pragma unroll
        for (int h = 0; h < 2; h++) {
            int d = tid + h * 256;
            float v = 0.f;
            #pragma unroll
            for (int c = 0; c < NCH * 2; c++)
                v += g_pp[((size_t)(s * NCH * 2 + c) * KTOP + k) * D + d];
            out[ob + k * D + d] = v;
        }
    }
}

// ------------------ launch ------------------
extern "C" void kernel_launch(void* const* d_in, const int* in_sizes, int n_in,
                              void* d_out, int out_size) {
    const float* probes  = (const float*)d_in[0];
    const float* gallery = (const float*)d_in[1];
    const int*   plen    = (const int*)d_in[2];
    const int*   glen    = (const int*)d_in[3];
    const float* proxP   = (const float*)d_in[4];
    const float* proxG   = (const float*)d_in[5];
    const float* tW      = (const float*)d_in[6];
    const float* tb      = (const float*)d_in[7];
    const float* probeW  = (const float*)d_in[8];
    const float* probeB  = (const float*)d_in[9];
    const float* W1      = (const float*)d_in[10];
    const float* b1      = (const float*)d_in[11];
    const float* W2      = (const float*)d_in[12];
    const float* b2      = (const float*)d_in[13];
    const float* W3      = (const float*)d_in[14];
    const float* b3      = (const float*)d_in[15];
    float* out = (float*)d_out;

    float *h1, *h2, *ctxv, *sum;
    cudaGetSymbolAddress((void**)&h1, g_h1);
    cudaGetSymbolAddress((void**)&h2, g_h2);
    cudaGetSymbolAddress((void**)&ctxv, g_ctxv);
    cudaGetSymbolAddress((void**)&sum, g_sum);

    cudaFuncSetAttribute(k_mlp_t<1536, 1024>, cudaFuncAttributeMaxDynamicSharedMemorySize, SMEM_MLP);
    cudaFuncSetAttribute(k_mlp_t<1024, 1024>, cudaFuncAttributeMaxDynamicSharedMemorySize, SMEM_MLP);
    cudaFuncSetAttribute(k_mlp_t<1024,  512>, cudaFuncAttributeMaxDynamicSharedMemorySize, SMEM_MLP);

    k_init<<<1, 256>>>(proxP, proxG, tW, tb, out);
    k_fuse1<<<dim3(NSET, NCH), 256>>>(probes, gallery, plen, glen, tW);
    k_prep<<<NSET, 256>>>(plen, glen, proxP, proxG);
    k_mlp_t<1536, 1024><<<dim3(KALL, 8, 12), 256, SMEM_MLP>>>(W1, b1, sum, h1);
    k_mlp_t<1024, 1024><<<dim3(KALL, 8, 12), 256, SMEM_MLP>>>(W2, b2, h1, h2);
    k_mlp_t<1024,  512><<<dim3(KALL, 4, 12), 256, SMEM_MLP>>>(W3, b3, h2, ctxv);
    k_ctx2gemm<<<dim3(8, 8), 256>>>(probeW);
    k_scores<<<dim3(NSET, NCH), 256>>>(probes, gallery, plen, glen, probeB);
    k_poolacc<<<dim3(NSET, NCH), 256>>>(probes, gallery, plen, glen);
    k_poolred<<<NSET, 256>>>(out);
}